// round 7
// baseline (speedup 1.0000x reference)
#include <cuda_runtime.h>
#include <cuda_bf16.h>
#include <math.h>

// Problem constants
#define N_TOKENS   32768
#define HIDDEN     2048
#define N_EXPERTS  256
#define N_GROUP    8
#define TOPK_GROUP 4
#define TOP_K      8
#define ROUTED_SCALING 2.5f

// Eigen threaded contraction k-blocking, k_cache capped at 320:
// kc = 320 -> chunks {320 x 6, 128}. BK=8 -> 40 tiles per chunk.
#define KC_TILES 40
#define LAST_FLUSH_TILE 239   // flush after tiles 39,79,...,239; tail = 128 k

// ---------------------------------------------------------------------------
// XLA CPU GenerateVF32Exp (llvm_ir_runtime, Cephes): fused MulAdds, unfused
// range reduction. (Irrelevant for idx decisions per R1==R6, kept for weights.)
// ---------------------------------------------------------------------------
__device__ __forceinline__ float xla_expf(float v) {
    float x = fminf(fmaxf(v, -88.3762626647949f), 88.3762626647950f);
    float fx = floorf(fmaf(x, 1.44269504088896341f, 0.5f));
    float tmp = __fmul_rn(fx, 0.693359375f);
    float z2  = __fmul_rn(fx, -2.12194440e-4f);
    x = __fsub_rn(x, tmp);
    x = __fsub_rn(x, z2);
    float zz = __fmul_rn(x, x);
    float y = 1.9875691500E-4f;
    y = fmaf(y, x, 1.3981999507E-3f);
    y = fmaf(y, x, 8.3334519073E-3f);
    y = fmaf(y, x, 4.1665795894E-2f);
    y = fmaf(y, x, 1.6666665459E-1f);
    y = fmaf(y, x, 5.0000001201E-1f);
    y = fmaf(y, zz, x);
    y = __fadd_rn(y, 1.0f);
    int n = (int)fx;
    float p2n = __int_as_float((n + 127) << 23);
    return __fmul_rn(y, p2n);
}

__device__ __forceinline__ float ref_sigmoid(float L) {
    return __fdiv_rn(1.0f, __fadd_rn(1.0f, xla_expf(-L)));
}

// ---------------------------------------------------------------------------
// GEMM: C[M,E] = A[M,K] * B[E,K]^T, fp32.
// Per element: serial fused-fma chains within kc=320 panels; panels joined
// by single fadd into the running total (Eigen gebp beta-accumulate).
// BM=128, BN=128, BK=8, 256 threads, 8x8 per thread.
// ---------------------------------------------------------------------------
#define BM 128
#define BN 128
#define BK 8

__global__ __launch_bounds__(256, 2)
void gate_gemm_kernel(const float* __restrict__ A,
                      const float* __restrict__ B,
                      float* __restrict__ C)
{
    __shared__ float As[BK][BM];
    __shared__ float Bs[BK][BN];

    const int tid = threadIdx.x;
    const int tx  = tid & 15;
    const int ty  = tid >> 4;

    const int rowBase = blockIdx.y * BM;
    const int colBase = blockIdx.x * BN;

    const int lr = tid >> 1;
    const int lc = (tid & 1) * 4;

    const float* Aptr = A + (size_t)(rowBase + lr) * HIDDEN + lc;
    const float* Bptr = B + (size_t)(colBase + lr) * HIDDEN + lc;

    float cur[8][8], tot[8][8];
#pragma unroll
    for (int i = 0; i < 8; i++)
#pragma unroll
        for (int j = 0; j < 8; j++) { cur[i][j] = 0.0f; tot[i][j] = 0.0f; }

    for (int t = 0; t < HIDDEN / BK; ++t) {
        const int k = t * BK;
        float4 a = *(const float4*)(Aptr + k);
        float4 b = *(const float4*)(Bptr + k);
        As[lc + 0][lr] = a.x; As[lc + 1][lr] = a.y;
        As[lc + 2][lr] = a.z; As[lc + 3][lr] = a.w;
        Bs[lc + 0][lr] = b.x; Bs[lc + 1][lr] = b.y;
        Bs[lc + 2][lr] = b.z; Bs[lc + 3][lr] = b.w;
        __syncthreads();

#pragma unroll
        for (int kk = 0; kk < BK; kk++) {
            float ra[8], rb[8];
            float4 ra0 = *(const float4*)&As[kk][ty * 8];
            float4 ra1 = *(const float4*)&As[kk][ty * 8 + 4];
            float4 rb0 = *(const float4*)&Bs[kk][tx * 8];
            float4 rb1 = *(const float4*)&Bs[kk][tx * 8 + 4];
            ra[0]=ra0.x; ra[1]=ra0.y; ra[2]=ra0.z; ra[3]=ra0.w;
            ra[4]=ra1.x; ra[5]=ra1.y; ra[6]=ra1.z; ra[7]=ra1.w;
            rb[0]=rb0.x; rb[1]=rb0.y; rb[2]=rb0.z; rb[3]=rb0.w;
            rb[4]=rb1.x; rb[5]=rb1.y; rb[6]=rb1.z; rb[7]=rb1.w;
#pragma unroll
            for (int i = 0; i < 8; i++)
#pragma unroll
                for (int j = 0; j < 8; j++)
                    cur[i][j] = fmaf(ra[i], rb[j], cur[i][j]);
        }
        __syncthreads();

        // kc=320 panel boundary: flush after tiles 39, 79, ..., 239
        if ((t % KC_TILES) == (KC_TILES - 1) && t <= LAST_FLUSH_TILE) {
#pragma unroll
            for (int i = 0; i < 8; i++)
#pragma unroll
                for (int j = 0; j < 8; j++) {
                    tot[i][j] = __fadd_rn(tot[i][j], cur[i][j]);
                    cur[i][j] = 0.0f;
                }
        }
    }
    // tail panel (last 128 k)
#pragma unroll
    for (int i = 0; i < 8; i++)
#pragma unroll
        for (int j = 0; j < 8; j++)
            tot[i][j] = __fadd_rn(tot[i][j], cur[i][j]);

#pragma unroll
    for (int i = 0; i < 8; i++) {
        const int m = rowBase + ty * 8 + i;
        float* crow = C + (size_t)m * N_EXPERTS + colBase + tx * 8;
        *(float4*)(crow)     = make_float4(tot[i][0], tot[i][1], tot[i][2], tot[i][3]);
        *(float4*)(crow + 4) = make_float4(tot[i][4], tot[i][5], tot[i][6], tot[i][7]);
    }
}

// ---------------------------------------------------------------------------
// Routing. One block (256 threads) per token. Ties -> lower index (stable).
// ---------------------------------------------------------------------------
__global__ __launch_bounds__(256)
void routing_kernel(const float* __restrict__ logits,
                    const float* __restrict__ bias,
                    float* __restrict__ out_idx,
                    float* __restrict__ out_w)
{
    const int token = blockIdx.x;
    const int tid   = threadIdx.x;
    const int lane  = tid & 31;
    const int warp  = tid >> 5;

    __shared__ float sraw[N_EXPERTS];
    __shared__ float sc[N_EXPERTS];
    __shared__ float gscore[N_GROUP];
    __shared__ int   gmask[N_GROUP];
    __shared__ int   selidx[TOP_K];
    __shared__ float selsc[TOP_K];

    const float L = logits[(size_t)token * N_EXPERTS + tid];
    const float s = ref_sigmoid(L);
    const float r = __fadd_rn(s, bias[tid]);
    sraw[tid] = s;

    // group top-2 (warp = group); group score = a + b, a >= b
    float a = r, b = -INFINITY;
#pragma unroll
    for (int off = 16; off; off >>= 1) {
        float oa = __shfl_xor_sync(0xffffffffu, a, off);
        float ob = __shfl_xor_sync(0xffffffffu, b, off);
        if (oa > a) { b = fmaxf(a, ob); a = oa; }
        else        { b = fmaxf(b, oa); }
    }
    if (lane == 0) gscore[warp] = __fadd_rn(a, b);
    __syncthreads();

    // top-4 groups, tie -> lower index
    if (tid == 0) {
        float g[N_GROUP];
#pragma unroll
        for (int i = 0; i < N_GROUP; i++) g[i] = gscore[i];
        int chosen = 0;
#pragma unroll
        for (int sel = 0; sel < TOPK_GROUP; sel++) {
            float best = -INFINITY; int bi = 0;
            for (int i = 0; i < N_GROUP; i++)
                if (!((chosen >> i) & 1) && g[i] > best) { best = g[i]; bi = i; }
            chosen |= (1 << bi);
        }
#pragma unroll
        for (int i = 0; i < N_GROUP; i++) gmask[i] = (chosen >> i) & 1;
    }
    __syncthreads();

    sc[tid] = gmask[warp] ? r : -INFINITY;
    __syncthreads();

    // top-8 experts (warp 0), stable tie-break
    if (warp == 0) {
        float v[8];
#pragma unroll
        for (int j = 0; j < 8; j++) v[j] = sc[j * 32 + lane];

#pragma unroll
        for (int it = 0; it < TOP_K; it++) {
            float bv = -INFINITY; int bj = 0;
#pragma unroll
            for (int j = 0; j < 8; j++)
                if (v[j] > bv) { bv = v[j]; bj = j; }   // tie -> lower j
            float mv = bv;
            int   mi = bj * 32 + lane;
#pragma unroll
            for (int off = 16; off; off >>= 1) {
                float ov = __shfl_xor_sync(0xffffffffu, mv, off);
                int   oi = __shfl_xor_sync(0xffffffffu, mi, off);
                if (ov > mv || (ov == mv && oi < mi)) { mv = ov; mi = oi; }
            }
#pragma unroll
            for (int j = 0; j < 8; j++)
                if (mi == j * 32 + lane) v[j] = -INFINITY;
            if (lane == it) selidx[it] = mi;
        }
        __syncwarp();

        if (lane < TOP_K) selsc[lane] = sraw[selidx[lane]];
        __syncwarp();

        if (lane < TOP_K) {
            float sum = selsc[0];
#pragma unroll
            for (int j = 1; j < TOP_K; j++) sum = __fadd_rn(sum, selsc[j]);
            const float w = __fmul_rn(
                __fdiv_rn(selsc[lane], __fadd_rn(sum, 1e-20f)), ROUTED_SCALING);
            out_idx[(size_t)token * TOP_K + lane] = (float)selidx[lane];
            out_w  [(size_t)token * TOP_K + lane] = w;
        }
    }
}

// ---------------------------------------------------------------------------
extern "C" void kernel_launch(void* const* d_in, const int* in_sizes, int n_in,
                              void* d_out, int out_size)
{
    const float* hs   = (const float*)d_in[0];
    const float* w    = (const float*)d_in[1];
    const float* bias = (const float*)d_in[2];

    float* out = (float*)d_out;
    float* out_idx    = out;
    float* out_w      = out + (size_t)N_TOKENS * TOP_K;
    float* out_logits = out + (size_t)N_TOKENS * TOP_K * 2;

    dim3 gemm_grid(N_EXPERTS / BN, N_TOKENS / BM);   // (2, 256)
    gate_gemm_kernel<<<gemm_grid, 256>>>(hs, w, out_logits);

    routing_kernel<<<N_TOKENS, 256>>>(out_logits, bias, out_idx, out_w);
}

// round 8
// speedup vs baseline: 1.0553x; 1.0553x over previous
#include <cuda_runtime.h>
#include <cuda_bf16.h>
#include <math.h>

// Problem constants
#define N_TOKENS   32768
#define HIDDEN     2048
#define N_EXPERTS  256
#define N_GROUP    8
#define TOPK_GROUP 4
#define TOP_K      8
#define ROUTED_SCALING 2.5f

// Eigen threaded contraction k-blocking: kc=320 -> panels {320 x 6, 128}.
// BK=8 -> 40 tiles per panel; flush after tiles 39,79,...,239; tail = 128 k.
#define KC_TILES 40
#define LAST_FLUSH_TILE 239

// ---------------------------------------------------------------------------
// Packed f32x2 helpers (sm_103a). Each lane is IEEE rn — bit-identical to the
// scalar fmaf/__fadd_rn chains, two outputs per issue slot.
// ---------------------------------------------------------------------------
__device__ __forceinline__ unsigned long long pack2(float lo, float hi) {
    unsigned long long r;
    asm("mov.b64 %0, {%1, %2};" : "=l"(r) : "f"(lo), "f"(hi));
    return r;
}
__device__ __forceinline__ void unpack2(unsigned long long v, float& lo, float& hi) {
    asm("mov.b64 {%0, %1}, %2;" : "=f"(lo), "=f"(hi) : "l"(v));
}
__device__ __forceinline__ void fma2(unsigned long long& d,
                                     unsigned long long a, unsigned long long b) {
    asm("fma.rn.f32x2 %0, %1, %2, %0;" : "+l"(d) : "l"(a), "l"(b));
}
__device__ __forceinline__ void add2(unsigned long long& d, unsigned long long a) {
    asm("add.rn.f32x2 %0, %0, %1;" : "+l"(d) : "l"(a));
}

// ---------------------------------------------------------------------------
// XLA CPU GenerateVF32Exp (llvm_ir_runtime, Cephes) — bit-pinned.
// ---------------------------------------------------------------------------
__device__ __forceinline__ float xla_expf(float v) {
    float x = fminf(fmaxf(v, -88.3762626647949f), 88.3762626647950f);
    float fx = floorf(fmaf(x, 1.44269504088896341f, 0.5f));
    float tmp = __fmul_rn(fx, 0.693359375f);
    float z2  = __fmul_rn(fx, -2.12194440e-4f);
    x = __fsub_rn(x, tmp);
    x = __fsub_rn(x, z2);
    float zz = __fmul_rn(x, x);
    float y = 1.9875691500E-4f;
    y = fmaf(y, x, 1.3981999507E-3f);
    y = fmaf(y, x, 8.3334519073E-3f);
    y = fmaf(y, x, 4.1665795894E-2f);
    y = fmaf(y, x, 1.6666665459E-1f);
    y = fmaf(y, x, 5.0000001201E-1f);
    y = fmaf(y, zz, x);
    y = __fadd_rn(y, 1.0f);
    int n = (int)fx;
    float p2n = __int_as_float((n + 127) << 23);
    return __fmul_rn(y, p2n);
}

__device__ __forceinline__ float ref_sigmoid(float L) {
    return __fdiv_rn(1.0f, __fadd_rn(1.0f, xla_expf(-L)));
}

// ---------------------------------------------------------------------------
// GEMM: C[M,E] = A[M,K] * B[E,K]^T, fp32, FFMA2-packed (2 cols per 64-bit acc).
// Per element: serial fma chain within kc=320 panels, fadd joins — bit-exact
// Eigen gebp emulation, identical to R7 arithmetic.
// BM=128, BN=128, BK=8, 256 threads, 8 rows x 4 col-pairs per thread.
// ---------------------------------------------------------------------------
#define BM 128
#define BN 128
#define BK 8

__global__ __launch_bounds__(256, 2)
void gate_gemm_kernel(const float* __restrict__ A,
                      const float* __restrict__ B,
                      float* __restrict__ C)
{
    __shared__ float As[BK][BM];
    __shared__ float Bs[BK][BN];

    const int tid = threadIdx.x;
    const int tx  = tid & 15;
    const int ty  = tid >> 4;

    const int rowBase = blockIdx.y * BM;
    const int colBase = blockIdx.x * BN;

    const int lr = tid >> 1;
    const int lc = (tid & 1) * 4;

    const float* Aptr = A + (size_t)(rowBase + lr) * HIDDEN + lc;
    const float* Bptr = B + (size_t)(colBase + lr) * HIDDEN + lc;

    unsigned long long cur[8][4], tot[8][4];
    const unsigned long long z2v = pack2(0.0f, 0.0f);
#pragma unroll
    for (int i = 0; i < 8; i++)
#pragma unroll
        for (int j = 0; j < 4; j++) { cur[i][j] = z2v; tot[i][j] = z2v; }

    for (int t = 0; t < HIDDEN / BK; ++t) {
        const int k = t * BK;
        float4 a = *(const float4*)(Aptr + k);
        float4 b = *(const float4*)(Bptr + k);
        As[lc + 0][lr] = a.x; As[lc + 1][lr] = a.y;
        As[lc + 2][lr] = a.z; As[lc + 3][lr] = a.w;
        Bs[lc + 0][lr] = b.x; Bs[lc + 1][lr] = b.y;
        Bs[lc + 2][lr] = b.z; Bs[lc + 3][lr] = b.w;
        __syncthreads();

#pragma unroll
        for (int kk = 0; kk < BK; kk++) {
            float4 ra0 = *(const float4*)&As[kk][ty * 8];
            float4 ra1 = *(const float4*)&As[kk][ty * 8 + 4];
            float4 rb0 = *(const float4*)&Bs[kk][tx * 8];
            float4 rb1 = *(const float4*)&Bs[kk][tx * 8 + 4];

            // b column-pairs: components already adjacent in regs
            unsigned long long b2[4];
            b2[0] = pack2(rb0.x, rb0.y);
            b2[1] = pack2(rb0.z, rb0.w);
            b2[2] = pack2(rb1.x, rb1.y);
            b2[3] = pack2(rb1.z, rb1.w);

            // a broadcast pairs
            float ra[8];
            ra[0]=ra0.x; ra[1]=ra0.y; ra[2]=ra0.z; ra[3]=ra0.w;
            ra[4]=ra1.x; ra[5]=ra1.y; ra[6]=ra1.z; ra[7]=ra1.w;
#pragma unroll
            for (int i = 0; i < 8; i++) {
                unsigned long long a2 = pack2(ra[i], ra[i]);
#pragma unroll
                for (int j = 0; j < 4; j++)
                    fma2(cur[i][j], a2, b2[j]);
            }
        }
        __syncthreads();

        // kc=320 panel boundary: flush after tiles 39, 79, ..., 239
        if ((t % KC_TILES) == (KC_TILES - 1) && t <= LAST_FLUSH_TILE) {
#pragma unroll
            for (int i = 0; i < 8; i++)
#pragma unroll
                for (int j = 0; j < 4; j++) {
                    add2(tot[i][j], cur[i][j]);
                    cur[i][j] = z2v;
                }
        }
    }
    // tail panel (last 128 k)
#pragma unroll
    for (int i = 0; i < 8; i++)
#pragma unroll
        for (int j = 0; j < 4; j++)
            add2(tot[i][j], cur[i][j]);

#pragma unroll
    for (int i = 0; i < 8; i++) {
        const int m = rowBase + ty * 8 + i;
        float* crow = C + (size_t)m * N_EXPERTS + colBase + tx * 8;
        float c0,c1,c2,c3,c4,c5,c6,c7;
        unpack2(tot[i][0], c0, c1);
        unpack2(tot[i][1], c2, c3);
        unpack2(tot[i][2], c4, c5);
        unpack2(tot[i][3], c6, c7);
        *(float4*)(crow)     = make_float4(c0, c1, c2, c3);
        *(float4*)(crow + 4) = make_float4(c4, c5, c6, c7);
    }
}

// ---------------------------------------------------------------------------
// Routing. One block (256 threads) per token. Ties -> lower index (stable).
// ---------------------------------------------------------------------------
__global__ __launch_bounds__(256)
void routing_kernel(const float* __restrict__ logits,
                    const float* __restrict__ bias,
                    float* __restrict__ out_idx,
                    float* __restrict__ out_w)
{
    const int token = blockIdx.x;
    const int tid   = threadIdx.x;
    const int lane  = tid & 31;
    const int warp  = tid >> 5;

    __shared__ float sraw[N_EXPERTS];
    __shared__ float sc[N_EXPERTS];
    __shared__ float gscore[N_GROUP];
    __shared__ int   gmask[N_GROUP];
    __shared__ int   selidx[TOP_K];
    __shared__ float selsc[TOP_K];

    const float L = logits[(size_t)token * N_EXPERTS + tid];
    const float s = ref_sigmoid(L);
    const float r = __fadd_rn(s, bias[tid]);
    sraw[tid] = s;

    // group top-2 (warp = group); group score = a + b, a >= b
    float a = r, b = -INFINITY;
#pragma unroll
    for (int off = 16; off; off >>= 1) {
        float oa = __shfl_xor_sync(0xffffffffu, a, off);
        float ob = __shfl_xor_sync(0xffffffffu, b, off);
        if (oa > a) { b = fmaxf(a, ob); a = oa; }
        else        { b = fmaxf(b, oa); }
    }
    if (lane == 0) gscore[warp] = __fadd_rn(a, b);
    __syncthreads();

    // top-4 groups, tie -> lower index
    if (tid == 0) {
        float g[N_GROUP];
#pragma unroll
        for (int i = 0; i < N_GROUP; i++) g[i] = gscore[i];
        int chosen = 0;
#pragma unroll
        for (int sel = 0; sel < TOPK_GROUP; sel++) {
            float best = -INFINITY; int bi = 0;
            for (int i = 0; i < N_GROUP; i++)
                if (!((chosen >> i) & 1) && g[i] > best) { best = g[i]; bi = i; }
            chosen |= (1 << bi);
        }
#pragma unroll
        for (int i = 0; i < N_GROUP; i++) gmask[i] = (chosen >> i) & 1;
    }
    __syncthreads();

    sc[tid] = gmask[warp] ? r : -INFINITY;
    __syncthreads();

    // top-8 experts (warp 0), stable tie-break
    if (warp == 0) {
        float v[8];
#pragma unroll
        for (int j = 0; j < 8; j++) v[j] = sc[j * 32 + lane];

#pragma unroll
        for (int it = 0; it < TOP_K; it++) {
            float bv = -INFINITY; int bj = 0;
#pragma unroll
            for (int j = 0; j < 8; j++)
                if (v[j] > bv) { bv = v[j]; bj = j; }   // tie -> lower j
            float mv = bv;
            int   mi = bj * 32 + lane;
#pragma unroll
            for (int off = 16; off; off >>= 1) {
                float ov = __shfl_xor_sync(0xffffffffu, mv, off);
                int   oi = __shfl_xor_sync(0xffffffffu, mi, off);
                if (ov > mv || (ov == mv && oi < mi)) { mv = ov; mi = oi; }
            }
#pragma unroll
            for (int j = 0; j < 8; j++)
                if (mi == j * 32 + lane) v[j] = -INFINITY;
            if (lane == it) selidx[it] = mi;
        }
        __syncwarp();

        if (lane < TOP_K) selsc[lane] = sraw[selidx[lane]];
        __syncwarp();

        if (lane < TOP_K) {
            float sum = selsc[0];
#pragma unroll
            for (int j = 1; j < TOP_K; j++) sum = __fadd_rn(sum, selsc[j]);
            const float w = __fmul_rn(
                __fdiv_rn(selsc[lane], __fadd_rn(sum, 1e-20f)), ROUTED_SCALING);
            out_idx[(size_t)token * TOP_K + lane] = (float)selidx[lane];
            out_w  [(size_t)token * TOP_K + lane] = w;
        }
    }
}

// ---------------------------------------------------------------------------
extern "C" void kernel_launch(void* const* d_in, const int* in_sizes, int n_in,
                              void* d_out, int out_size)
{
    const float* hs   = (const float*)d_in[0];
    const float* w    = (const float*)d_in[1];
    const float* bias = (const float*)d_in[2];

    float* out = (float*)d_out;
    float* out_idx    = out;
    float* out_w      = out + (size_t)N_TOKENS * TOP_K;
    float* out_logits = out + (size_t)N_TOKENS * TOP_K * 2;

    dim3 gemm_grid(N_EXPERTS / BN, N_TOKENS / BM);   // (2, 256)
    gate_gemm_kernel<<<gemm_grid, 256>>>(hs, w, out_logits);

    routing_kernel<<<N_TOKENS, 256>>>(out_logits, bias, out_idx, out_w);
}